// round 3
// baseline (speedup 1.0000x reference)
#include <cuda_runtime.h>

// CausalDAG fused kernel for GB300 (sm_103a)
//   m[b,i,d]  = sum_j A[j,i] * x[b,j,d]
//   h[b,c,g]  = elu( sum_d W1[c,g,d] * m[b,c,d] + b1[c,g] )
//   out[b,c,d]= sum_g W2[c,d,g] * h[b,c,g] + b2[c,d]
//
// Strategy: one CTA (512 threads) per 32-batch tile.
//   Phase 1: threads (b,dchunk) compute m into smem [c][b][d]  (STS.128 contiguous)
//   Phase 2: warp = concept c, lane = g. W1 row register-cached as packed f32x2.
//            m rows read as warp-broadcast LDS.128 (conflict-free, 1 crossbar phase).
//   Phase 3: warp = c, lane owns d and d+32. W2 rows register-cached, h broadcast.
// All hot-loop FMAs use Blackwell packed fp32 (fma.rn.f32x2) -> 2 MACs/issue,
// bit-exact fp32 per element.

#define Cc 16
#define Dd 64
#define Gg 32
#define BT 32
#define NTHREADS 512

typedef unsigned long long ull;

__device__ __forceinline__ ull fma2(ull a, ull b, ull c) {
    ull d;
    asm("fma.rn.f32x2 %0, %1, %2, %3;" : "=l"(d) : "l"(a), "l"(b), "l"(c));
    return d;
}
__device__ __forceinline__ ull dup2(float a) {
    ull d;
    asm("mov.b64 %0, {%1, %1};" : "=l"(d) : "f"(a));
    return d;
}
__device__ __forceinline__ float hsum2(ull v) {
    float lo, hi;
    asm("mov.b64 {%0, %1}, %2;" : "=f"(lo), "=f"(hi) : "l"(v));
    return lo + hi;
}

extern __shared__ float smem[];

__global__ void __launch_bounds__(NTHREADS, 1)
causal_dag_kernel(const float* __restrict__ x,  const float* __restrict__ A,
                  const float* __restrict__ W1, const float* __restrict__ b1,
                  const float* __restrict__ W2, const float* __restrict__ b2,
                  float* __restrict__ out)
{
    float* m_s = smem;                    // [C][BT][D]  = 32768 floats (128 KB)
    float* h_s = smem + Cc * BT * Dd;     // [C][BT][G]  = 16384 floats (64 KB)
    float* A_s = h_s + Cc * BT * Gg;      // [C][C]      = 256 floats

    const int tid = threadIdx.x;
    const int b0  = blockIdx.x * BT;

    if (tid < Cc * Cc) A_s[tid] = A[tid];
    __syncthreads();

    // ---------------- Phase 1: mix  m[c][b][d] = sum_j A[j,c] x[b,j,d] -------
    {
        const int bl = tid >> 4;          // 0..31 : local batch element
        const int dq = tid & 15;          // 0..15 : float4 chunk within D=64
        const ulonglong2* xb =
            (const ulonglong2*)(x + (size_t)(b0 + bl) * (Cc * Dd));

        ull mrx[Cc], mrz[Cc];             // packed pairs: (d,d+1) and (d+2,d+3)
        #pragma unroll
        for (int i = 0; i < Cc; i++) { mrx[i] = 0ull; mrz[i] = 0ull; }

        #pragma unroll
        for (int j = 0; j < Cc; j++) {
            ulonglong2 xv = xb[j * 16 + dq];        // x[b][j][4dq..4dq+3]
            #pragma unroll
            for (int i = 0; i < Cc; i++) {
                ull a2 = dup2(A_s[j * Cc + i]);     // A[j,i] duplicated
                mrx[i] = fma2(a2, xv.x, mrx[i]);
                mrz[i] = fma2(a2, xv.y, mrz[i]);
            }
        }
        #pragma unroll
        for (int i = 0; i < Cc; i++) {
            ulonglong2 v; v.x = mrx[i]; v.y = mrz[i];
            // contiguous 512B per warp -> conflict-free STS.128
            *(ulonglong2*)&m_s[(i * BT + bl) * Dd + dq * 4] = v;
        }
    }
    __syncthreads();

    const int c    = tid >> 5;            // warp id == concept
    const int lane = tid & 31;

    // ---------------- Phase 2: h = elu(W1_c @ m_c + b1) ----------------------
    {
        // lane g caches W1[c][g][0..63] as 32 packed f32x2 pairs
        const ulonglong2* wrow =
            (const ulonglong2*)(W1 + (size_t)(c * Gg + lane) * Dd);
        ull w1q[32];
        #pragma unroll
        for (int k = 0; k < 16; k++) {
            ulonglong2 t = wrow[k];
            w1q[2 * k] = t.x; w1q[2 * k + 1] = t.y;
        }
        const float bias = b1[c * Gg + lane];

        for (int bl = 0; bl < BT; bl++) {
            // whole-warp broadcast reads: 1 crossbar phase per LDS.128
            const ulonglong2* mrow =
                (const ulonglong2*)&m_s[(c * BT + bl) * Dd];
            ull a0 = 0, a1 = 0, a2 = 0, a3 = 0;
            #pragma unroll
            for (int k = 0; k < 16; k += 2) {
                ulonglong2 m0 = mrow[k];
                ulonglong2 m1 = mrow[k + 1];
                a0 = fma2(w1q[2 * k],     m0.x, a0);
                a1 = fma2(w1q[2 * k + 1], m0.y, a1);
                a2 = fma2(w1q[2 * k + 2], m1.x, a2);
                a3 = fma2(w1q[2 * k + 3], m1.y, a3);
            }
            float hpre = (hsum2(a0) + hsum2(a1)) + (hsum2(a2) + hsum2(a3)) + bias;
            float hv = hpre > 0.0f ? hpre : expm1f(hpre);   // jax.nn.elu, alpha=1
            h_s[(c * BT + bl) * Gg + lane] = hv;            // lanes contiguous
        }
    }
    __syncthreads();

    // ---------------- Phase 3: out = W2_c @ h + b2 ---------------------------
    {
        const int d0 = lane;
        const int d1 = lane + 32;
        const ulonglong2* wr0 =
            (const ulonglong2*)(W2 + (size_t)(c * Dd + d0) * Gg);
        const ulonglong2* wr1 =
            (const ulonglong2*)(W2 + (size_t)(c * Dd + d1) * Gg);
        ull w2a[16], w2b[16];
        #pragma unroll
        for (int k = 0; k < 8; k++) {
            ulonglong2 ta = wr0[k]; w2a[2 * k] = ta.x; w2a[2 * k + 1] = ta.y;
            ulonglong2 tb = wr1[k]; w2b[2 * k] = tb.x; w2b[2 * k + 1] = tb.y;
        }
        const float bias0 = b2[c * Dd + d0];
        const float bias1 = b2[c * Dd + d1];

        for (int bl = 0; bl < BT; bl++) {
            const ulonglong2* hrow =
                (const ulonglong2*)&h_s[(c * BT + bl) * Gg];
            ull a0 = 0, a1 = 0, q0 = 0, q1 = 0;
            #pragma unroll
            for (int k = 0; k < 8; k++) {
                ulonglong2 hv = hrow[k];                    // broadcast
                a0 = fma2(w2a[2 * k],     hv.x, a0);
                a1 = fma2(w2a[2 * k + 1], hv.y, a1);
                q0 = fma2(w2b[2 * k],     hv.x, q0);
                q1 = fma2(w2b[2 * k + 1], hv.y, q1);
            }
            const float o0 = hsum2(a0) + hsum2(a1) + bias0;
            const float o1 = hsum2(q0) + hsum2(q1) + bias1;
            const size_t base = ((size_t)(b0 + bl) * Cc + c) * Dd;
            out[base + d0] = o0;     // lanes d0=0..31 -> one 128B STG
            out[base + d1] = o1;     // lanes d1=32..63 -> one 128B STG
        }
    }
}

extern "C" void kernel_launch(void* const* d_in, const int* in_sizes, int n_in,
                              void* d_out, int out_size)
{
    const float* x  = (const float*)d_in[0];
    const float* A  = (const float*)d_in[1];
    const float* W1 = (const float*)d_in[2];
    const float* b1 = (const float*)d_in[3];
    const float* W2 = (const float*)d_in[4];
    const float* b2 = (const float*)d_in[5];
    float* out = (float*)d_out;

    const int Btot = in_sizes[0] / (Cc * Dd);          // 65536
    const int smem_bytes = (Cc * BT * Dd + Cc * BT * Gg + Cc * Cc) * (int)sizeof(float); // 197632

    cudaFuncSetAttribute(causal_dag_kernel,
                         cudaFuncAttributeMaxDynamicSharedMemorySize, smem_bytes);

    causal_dag_kernel<<<Btot / BT, NTHREADS, smem_bytes>>>(x, A, W1, b1, W2, b2, out);
}

// round 4
// speedup vs baseline: 1.0040x; 1.0040x over previous
#include <cuda_runtime.h>

// CausalDAG fused kernel for GB300 (sm_103a)
//   m[b,i,d]  = sum_j A[j,i] * x[b,j,d]
//   h[b,c,g]  = elu( sum_d W1[c,g,d] * m[b,c,d] + b1[c,g] )
//   out[b,c,d]= sum_g W2[c,d,g] * h[b,c,g] + b2[c,d]
//
// Strategy: one CTA (512 threads) per 32-batch tile.
//   Phase 1: threads (b,dchunk) compute m into smem [c][b][d]  (STS.128 contiguous)
//   Phase 2: warp = concept c, lane = g. W1 row register-cached as packed f32x2.
//            m rows read as warp-broadcast LDS.128 (conflict-free, 1 crossbar phase).
//   Phase 3: warp = c, lane owns d and d+32. W2 rows register-cached, h broadcast.
// All hot-loop FMAs use Blackwell packed fp32 (fma.rn.f32x2) -> 2 MACs/issue,
// bit-exact fp32 per element.

#define Cc 16
#define Dd 64
#define Gg 32
#define BT 32
#define NTHREADS 512

typedef unsigned long long ull;

__device__ __forceinline__ ull fma2(ull a, ull b, ull c) {
    ull d;
    asm("fma.rn.f32x2 %0, %1, %2, %3;" : "=l"(d) : "l"(a), "l"(b), "l"(c));
    return d;
}
__device__ __forceinline__ ull dup2(float a) {
    ull d;
    asm("mov.b64 %0, {%1, %1};" : "=l"(d) : "f"(a));
    return d;
}
__device__ __forceinline__ float hsum2(ull v) {
    float lo, hi;
    asm("mov.b64 {%0, %1}, %2;" : "=f"(lo), "=f"(hi) : "l"(v));
    return lo + hi;
}

extern __shared__ float smem[];

__global__ void __launch_bounds__(NTHREADS, 1)
causal_dag_kernel(const float* __restrict__ x,  const float* __restrict__ A,
                  const float* __restrict__ W1, const float* __restrict__ b1,
                  const float* __restrict__ W2, const float* __restrict__ b2,
                  float* __restrict__ out)
{
    float* m_s = smem;                    // [C][BT][D]  = 32768 floats (128 KB)
    float* h_s = smem + Cc * BT * Dd;     // [C][BT][G]  = 16384 floats (64 KB)
    float* A_s = h_s + Cc * BT * Gg;      // [C][C]      = 256 floats

    const int tid = threadIdx.x;
    const int b0  = blockIdx.x * BT;

    if (tid < Cc * Cc) A_s[tid] = A[tid];
    __syncthreads();

    // ---------------- Phase 1: mix  m[c][b][d] = sum_j A[j,c] x[b,j,d] -------
    {
        const int bl = tid >> 4;          // 0..31 : local batch element
        const int dq = tid & 15;          // 0..15 : float4 chunk within D=64
        const ulonglong2* xb =
            (const ulonglong2*)(x + (size_t)(b0 + bl) * (Cc * Dd));

        ull mrx[Cc], mrz[Cc];             // packed pairs: (d,d+1) and (d+2,d+3)
        #pragma unroll
        for (int i = 0; i < Cc; i++) { mrx[i] = 0ull; mrz[i] = 0ull; }

        #pragma unroll
        for (int j = 0; j < Cc; j++) {
            ulonglong2 xv = xb[j * 16 + dq];        // x[b][j][4dq..4dq+3]
            #pragma unroll
            for (int i = 0; i < Cc; i++) {
                ull a2 = dup2(A_s[j * Cc + i]);     // A[j,i] duplicated
                mrx[i] = fma2(a2, xv.x, mrx[i]);
                mrz[i] = fma2(a2, xv.y, mrz[i]);
            }
        }
        #pragma unroll
        for (int i = 0; i < Cc; i++) {
            ulonglong2 v; v.x = mrx[i]; v.y = mrz[i];
            // contiguous 512B per warp -> conflict-free STS.128
            *(ulonglong2*)&m_s[(i * BT + bl) * Dd + dq * 4] = v;
        }
    }
    __syncthreads();

    const int c    = tid >> 5;            // warp id == concept
    const int lane = tid & 31;

    // ---------------- Phase 2: h = elu(W1_c @ m_c + b1) ----------------------
    {
        // lane g caches W1[c][g][0..63] as 32 packed f32x2 pairs
        const ulonglong2* wrow =
            (const ulonglong2*)(W1 + (size_t)(c * Gg + lane) * Dd);
        ull w1q[32];
        #pragma unroll
        for (int k = 0; k < 16; k++) {
            ulonglong2 t = wrow[k];
            w1q[2 * k] = t.x; w1q[2 * k + 1] = t.y;
        }
        const float bias = b1[c * Gg + lane];

        for (int bl = 0; bl < BT; bl++) {
            // whole-warp broadcast reads: 1 crossbar phase per LDS.128
            const ulonglong2* mrow =
                (const ulonglong2*)&m_s[(c * BT + bl) * Dd];
            ull a0 = 0, a1 = 0, a2 = 0, a3 = 0;
            #pragma unroll
            for (int k = 0; k < 16; k += 2) {
                ulonglong2 m0 = mrow[k];
                ulonglong2 m1 = mrow[k + 1];
                a0 = fma2(w1q[2 * k],     m0.x, a0);
                a1 = fma2(w1q[2 * k + 1], m0.y, a1);
                a2 = fma2(w1q[2 * k + 2], m1.x, a2);
                a3 = fma2(w1q[2 * k + 3], m1.y, a3);
            }
            float hpre = (hsum2(a0) + hsum2(a1)) + (hsum2(a2) + hsum2(a3)) + bias;
            float hv = hpre > 0.0f ? hpre : expm1f(hpre);   // jax.nn.elu, alpha=1
            h_s[(c * BT + bl) * Gg + lane] = hv;            // lanes contiguous
        }
    }
    __syncthreads();

    // ---------------- Phase 3: out = W2_c @ h + b2 ---------------------------
    {
        const int d0 = lane;
        const int d1 = lane + 32;
        const ulonglong2* wr0 =
            (const ulonglong2*)(W2 + (size_t)(c * Dd + d0) * Gg);
        const ulonglong2* wr1 =
            (const ulonglong2*)(W2 + (size_t)(c * Dd + d1) * Gg);
        ull w2a[16], w2b[16];
        #pragma unroll
        for (int k = 0; k < 8; k++) {
            ulonglong2 ta = wr0[k]; w2a[2 * k] = ta.x; w2a[2 * k + 1] = ta.y;
            ulonglong2 tb = wr1[k]; w2b[2 * k] = tb.x; w2b[2 * k + 1] = tb.y;
        }
        const float bias0 = b2[c * Dd + d0];
        const float bias1 = b2[c * Dd + d1];

        for (int bl = 0; bl < BT; bl++) {
            const ulonglong2* hrow =
                (const ulonglong2*)&h_s[(c * BT + bl) * Gg];
            ull a0 = 0, a1 = 0, q0 = 0, q1 = 0;
            #pragma unroll
            for (int k = 0; k < 8; k++) {
                ulonglong2 hv = hrow[k];                    // broadcast
                a0 = fma2(w2a[2 * k],     hv.x, a0);
                a1 = fma2(w2a[2 * k + 1], hv.y, a1);
                q0 = fma2(w2b[2 * k],     hv.x, q0);
                q1 = fma2(w2b[2 * k + 1], hv.y, q1);
            }
            const float o0 = hsum2(a0) + hsum2(a1) + bias0;
            const float o1 = hsum2(q0) + hsum2(q1) + bias1;
            const size_t base = ((size_t)(b0 + bl) * Cc + c) * Dd;
            out[base + d0] = o0;     // lanes d0=0..31 -> one 128B STG
            out[base + d1] = o1;     // lanes d1=32..63 -> one 128B STG
        }
    }
}

extern "C" void kernel_launch(void* const* d_in, const int* in_sizes, int n_in,
                              void* d_out, int out_size)
{
    const float* x  = (const float*)d_in[0];
    const float* A  = (const float*)d_in[1];
    const float* W1 = (const float*)d_in[2];
    const float* b1 = (const float*)d_in[3];
    const float* W2 = (const float*)d_in[4];
    const float* b2 = (const float*)d_in[5];
    float* out = (float*)d_out;

    const int Btot = in_sizes[0] / (Cc * Dd);          // 65536
    const int smem_bytes = (Cc * BT * Dd + Cc * BT * Gg + Cc * Cc) * (int)sizeof(float); // 197632

    cudaFuncSetAttribute(causal_dag_kernel,
                         cudaFuncAttributeMaxDynamicSharedMemorySize, smem_bytes);

    causal_dag_kernel<<<Btot / BT, NTHREADS, smem_bytes>>>(x, A, W1, b1, W2, b2, out);
}

// round 5
// speedup vs baseline: 1.1845x; 1.1798x over previous
#include <cuda_runtime.h>
#include <cstdint>

// CausalDAG fused kernel for GB300 (sm_103a)
//   m[b,i,d]  = sum_j A[j,i] * x[b,j,d]                      (fp32 fma2, exact)
//   h[b,c,g]  = elu( sum_d W1[c,g,d] * m[b,c,d] + b1[c,g] )  (TF32 3-mma comp)
//   out[b,c,d]= sum_g W2[c,d,g] * h[b,c,g] + b2[c,d]         (TF32 3-mma comp)
//
// CTA = 16-batch tile, 256 threads (8 warps). Warp w owns concepts 2w, 2w+1.
// Phase 1: SIMT fp32 packed-FMA mix -> m in smem, row stride 68 (conflict-free
//          fragment loads: bank = 4*grp + tig, all 32 distinct).
// Phase 2: mma.sync m16n8k8 tf32, A = m (smem frags), B = W1^T (global frags).
//          ELU in registers; H overwrites the warp-private m region (stride 36).
// Phase 3: mma.sync, A = H frags (regs, hoisted), B = W2^T, bias, STG.64 out.
// Error compensation: D += Ahi*Bhi + Alo*Bhi + Ahi*Blo  (fp32-level accuracy).

#define Cc 16
#define Dd 64
#define Gg 32
#define BT 16
#define DP 68          // m row stride (floats): 68 % 32 = 4 -> conflict-free frags
#define HP 36          // h row stride (floats): 36 % 32 = 4 -> conflict-free frags
#define NTH 256

typedef unsigned long long ull;

__device__ __forceinline__ ull fma2(ull a, ull b, ull c) {
    ull d;
    asm("fma.rn.f32x2 %0, %1, %2, %3;" : "=l"(d) : "l"(a), "l"(b), "l"(c));
    return d;
}
__device__ __forceinline__ ull dup2(float a) {
    ull d;
    asm("mov.b64 %0, {%1, %1};" : "=l"(d) : "f"(a));
    return d;
}

// Split fp32 into tf32 hi + tf32 lo (a - hi is fp32-exact; lo rounding ~2^-22 rel)
__device__ __forceinline__ void split_tf32(float v, uint32_t& hi, uint32_t& lo) {
    asm("cvt.rna.tf32.f32 %0, %1;" : "=r"(hi) : "f"(v));
    float r = v - __uint_as_float(hi);
    asm("cvt.rna.tf32.f32 %0, %1;" : "=r"(lo) : "f"(r));
}

__device__ __forceinline__ void mma_tf32(float c[4],
                                         uint32_t a0, uint32_t a1, uint32_t a2, uint32_t a3,
                                         uint32_t b0, uint32_t b1) {
    asm volatile(
        "mma.sync.aligned.m16n8k8.row.col.f32.tf32.tf32.f32 "
        "{%0,%1,%2,%3}, {%4,%5,%6,%7}, {%8,%9}, {%0,%1,%2,%3};"
        : "+f"(c[0]), "+f"(c[1]), "+f"(c[2]), "+f"(c[3])
        : "r"(a0), "r"(a1), "r"(a2), "r"(a3), "r"(b0), "r"(b1));
}

__device__ __forceinline__ void mma3(float c[4],
                                     const uint32_t ah[4], const uint32_t al[4],
                                     uint32_t bh0, uint32_t bh1,
                                     uint32_t bl0, uint32_t bl1) {
    mma_tf32(c, ah[0], ah[1], ah[2], ah[3], bh0, bh1);
    mma_tf32(c, al[0], al[1], al[2], al[3], bh0, bh1);
    mma_tf32(c, ah[0], ah[1], ah[2], ah[3], bl0, bl1);
}

extern __shared__ float smem[];

__global__ void __launch_bounds__(NTH, 2)
causal_dag_kernel(const float* __restrict__ x,  const float* __restrict__ A,
                  const float* __restrict__ W1, const float* __restrict__ b1,
                  const float* __restrict__ W2, const float* __restrict__ b2,
                  float* __restrict__ out)
{
    float* m_s = smem;                         // [C][BT][DP] = 17408 floats
    float* A_s = smem + Cc * BT * DP;          // [C][C] = 256 floats

    const int tid = threadIdx.x;
    const int b0  = blockIdx.x * BT;

    A_s[tid] = A[tid];                         // 256 threads == C*C elements
    __syncthreads();

    // ---------------- Phase 1: mix  m[c][bl][d] = sum_j A[j,c] x[b,j,d] ------
    {
        const int bl = tid >> 4;               // 0..15 local batch
        const int dq = tid & 15;               // 0..15 float4 chunk of D=64
        const ulonglong2* xb =
            (const ulonglong2*)(x + (size_t)(b0 + bl) * (Cc * Dd)) + dq;

        ull mrx[Cc], mrz[Cc];
        #pragma unroll
        for (int i = 0; i < Cc; i++) { mrx[i] = 0ull; mrz[i] = 0ull; }

        #pragma unroll
        for (int j = 0; j < Cc; j++) {
            ulonglong2 xv = xb[j * 16];        // x[b][j][4dq..4dq+3]
            #pragma unroll
            for (int i = 0; i < Cc; i++) {
                ull a2 = dup2(A_s[j * Cc + i]);
                mrx[i] = fma2(a2, xv.x, mrx[i]);
                mrz[i] = fma2(a2, xv.y, mrz[i]);
            }
        }
        #pragma unroll
        for (int i = 0; i < Cc; i++) {
            ulonglong2 v; v.x = mrx[i]; v.y = mrz[i];
            *(ulonglong2*)&m_s[i * (BT * DP) + bl * DP + dq * 4] = v;
        }
    }
    __syncthreads();

    // ---------------- Phases 2+3 on tensor cores -----------------------------
    const int w    = tid >> 5;                 // warp 0..7
    const int lane = tid & 31;
    const int grp  = lane >> 2;                // 0..7
    const int tig  = lane & 3;                 // 0..3

    #pragma unroll
    for (int s = 0; s < 2; s++) {
        const int cc = 2 * w + s;
        float* mc = m_s + cc * (BT * DP);      // warp-private concept tile

        // ---- Phase 2: H[16x32] = ELU(M[16x64] @ W1_cc^T + b1) ----
        float acc[4][4];
        #pragma unroll
        for (int nt = 0; nt < 4; nt++)
            #pragma unroll
            for (int q = 0; q < 4; q++) acc[nt][q] = 0.0f;

        const float* w1c = W1 + (size_t)cc * Gg * Dd;
        #pragma unroll
        for (int kt = 0; kt < 8; kt++) {
            const int colk = kt * 8 + tig;
            uint32_t ah[4], al[4];
            split_tf32(mc[grp * DP + colk],           ah[0], al[0]);
            split_tf32(mc[(grp + 8) * DP + colk],     ah[1], al[1]);
            split_tf32(mc[grp * DP + colk + 4],       ah[2], al[2]);
            split_tf32(mc[(grp + 8) * DP + colk + 4], ah[3], al[3]);
            #pragma unroll
            for (int nt = 0; nt < 4; nt++) {
                const float* bp = w1c + (nt * 8 + grp) * Dd + kt * 8 + tig;
                uint32_t bh0, bl0, bh1, bl1;
                split_tf32(bp[0], bh0, bl0);
                split_tf32(bp[4], bh1, bl1);
                mma3(acc[nt], ah, al, bh0, bh1, bl0, bl1);
            }
        }

        __syncwarp();                          // all m reads done before overwrite
        #pragma unroll
        for (int nt = 0; nt < 4; nt++) {
            const float2 bias = *(const float2*)&b1[cc * Gg + nt * 8 + 2 * tig];
            float h0 = acc[nt][0] + bias.x;
            float h1 = acc[nt][1] + bias.y;
            float h2 = acc[nt][2] + bias.x;
            float h3 = acc[nt][3] + bias.y;
            h0 = h0 > 0.0f ? h0 : expm1f(h0);
            h1 = h1 > 0.0f ? h1 : expm1f(h1);
            h2 = h2 > 0.0f ? h2 : expm1f(h2);
            h3 = h3 > 0.0f ? h3 : expm1f(h3);
            float2 v0; v0.x = h0; v0.y = h1;
            float2 v1; v1.x = h2; v1.y = h3;
            *(float2*)&mc[grp * HP + nt * 8 + 2 * tig]       = v0;  // row grp
            *(float2*)&mc[(grp + 8) * HP + nt * 8 + 2 * tig] = v1;  // row grp+8
        }
        __syncwarp();

        // ---- Phase 3: Out[16x64] = H[16x32] @ W2_cc^T + b2 ----
        // Hoist all H fragments (4 k-tiles) into registers, pre-split.
        uint32_t hh[4][4], hl[4][4];
        #pragma unroll
        for (int kt = 0; kt < 4; kt++) {
            const int colk = kt * 8 + tig;
            split_tf32(mc[grp * HP + colk],           hh[kt][0], hl[kt][0]);
            split_tf32(mc[(grp + 8) * HP + colk],     hh[kt][1], hl[kt][1]);
            split_tf32(mc[grp * HP + colk + 4],       hh[kt][2], hl[kt][2]);
            split_tf32(mc[(grp + 8) * HP + colk + 4], hh[kt][3], hl[kt][3]);
        }

        const float* w2c = W2 + (size_t)cc * Dd * Gg;
        #pragma unroll
        for (int nt = 0; nt < 8; nt++) {
            float o[4] = {0.0f, 0.0f, 0.0f, 0.0f};
            #pragma unroll
            for (int kt = 0; kt < 4; kt++) {
                const float* bp = w2c + (nt * 8 + grp) * Gg + kt * 8 + tig;
                uint32_t bh0, bl0, bh1, bl1;
                split_tf32(bp[0], bh0, bl0);
                split_tf32(bp[4], bh1, bl1);
                mma3(o, hh[kt], hl[kt], bh0, bh1, bl0, bl1);
            }
            const float2 bias = *(const float2*)&b2[cc * Dd + nt * 8 + 2 * tig];
            float2 v0; v0.x = o[0] + bias.x; v0.y = o[1] + bias.y;
            float2 v1; v1.x = o[2] + bias.x; v1.y = o[3] + bias.y;
            float* op0 = out + ((size_t)(b0 + grp) * Cc + cc) * Dd + nt * 8 + 2 * tig;
            float* op1 = out + ((size_t)(b0 + grp + 8) * Cc + cc) * Dd + nt * 8 + 2 * tig;
            *(float2*)op0 = v0;
            *(float2*)op1 = v1;
        }
    }
}

extern "C" void kernel_launch(void* const* d_in, const int* in_sizes, int n_in,
                              void* d_out, int out_size)
{
    const float* x  = (const float*)d_in[0];
    const float* A  = (const float*)d_in[1];
    const float* W1 = (const float*)d_in[2];
    const float* b1 = (const float*)d_in[3];
    const float* W2 = (const float*)d_in[4];
    const float* b2 = (const float*)d_in[5];
    float* out = (float*)d_out;

    const int Btot = in_sizes[0] / (Cc * Dd);                     // 65536
    const int smem_bytes = (Cc * BT * DP + Cc * Cc) * (int)sizeof(float); // 70656

    cudaFuncSetAttribute(causal_dag_kernel,
                         cudaFuncAttributeMaxDynamicSharedMemorySize, smem_bytes);

    causal_dag_kernel<<<Btot / BT, NTH, smem_bytes>>>(x, A, W1, b1, W2, b2, out);
}

// round 7
// speedup vs baseline: 1.6141x; 1.3627x over previous
#include <cuda_runtime.h>
#include <cstdint>

// CausalDAG fused kernel for GB300 (sm_103a), round 5.
//   m[b,i,d]  = sum_j A[j,i] * x[b,j,d]                      (fp32 fma2, exact)
//   h[b,c,g]  = elu( W1_c @ m + b1 )                         (TF32 3-mma comp)
//   out       = W2_c @ h + b2                                (TF32 3-mma comp)
//
// Changes vs R4:
//  * Prep kernel pre-splits W1/W2 into tf32 hi/lo, stored in fragment order:
//    one LDG.128 per thread yields a full B-fragment pair -> no per-CTA cvt/sub
//    ALU, no scattered scalar weight loads (this was 90.8% L1 + 32.8% alu).
//  * BT=32 (512 thr, warp = 1 concept, 2 M-row-tiles): halves weight L2 traffic.

#define Cc 16
#define Dd 64
#define Gg 32
#define BT 32
#define DP 68          // m row stride: bank(4*grp+tig) all distinct -> conflict-free
#define HP 36          // h row stride
#define NTH 512

typedef unsigned long long ull;

// Packed weight fragments: [c][kt(8)][ntp(2)][lane(32)] / [c][nt(8)][ktp(2)][lane(32)]
__device__ uint4 W1pHi[Cc * 8 * 2 * 32];
__device__ uint4 W1pLo[Cc * 8 * 2 * 32];
__device__ uint4 W2pHi[Cc * 8 * 2 * 32];
__device__ uint4 W2pLo[Cc * 8 * 2 * 32];

__device__ __forceinline__ ull fma2(ull a, ull b, ull c) {
    ull d;
    asm("fma.rn.f32x2 %0, %1, %2, %3;" : "=l"(d) : "l"(a), "l"(b), "l"(c));
    return d;
}
__device__ __forceinline__ ull dup2(float a) {
    ull d;
    asm("mov.b64 %0, {%1, %1};" : "=l"(d) : "f"(a));
    return d;
}
__device__ __forceinline__ void split_tf32(float v, uint32_t& hi, uint32_t& lo) {
    asm("cvt.rna.tf32.f32 %0, %1;" : "=r"(hi) : "f"(v));
    float r = v - __uint_as_float(hi);
    asm("cvt.rna.tf32.f32 %0, %1;" : "=r"(lo) : "f"(r));
}
__device__ __forceinline__ void mma_tf32(float c[4],
                                         uint32_t a0, uint32_t a1, uint32_t a2, uint32_t a3,
                                         uint32_t b0, uint32_t b1) {
    asm volatile(
        "mma.sync.aligned.m16n8k8.row.col.f32.tf32.tf32.f32 "
        "{%0,%1,%2,%3}, {%4,%5,%6,%7}, {%8,%9}, {%0,%1,%2,%3};"
        : "+f"(c[0]), "+f"(c[1]), "+f"(c[2]), "+f"(c[3])
        : "r"(a0), "r"(a1), "r"(a2), "r"(a3), "r"(b0), "r"(b1));
}
__device__ __forceinline__ void mma3(float c[4],
                                     const uint32_t ah[4], const uint32_t al[4],
                                     uint32_t bh0, uint32_t bh1,
                                     uint32_t bl0, uint32_t bl1) {
    mma_tf32(c, ah[0], ah[1], ah[2], ah[3], bh0, bh1);
    mma_tf32(c, al[0], al[1], al[2], al[3], bh0, bh1);
    mma_tf32(c, ah[0], ah[1], ah[2], ah[3], bl0, bl1);
}

// ---------------- Prep: pack weights into split fragment order ---------------
__global__ void __launch_bounds__(256)
pack_weights(const float* __restrict__ W1, const float* __restrict__ W2)
{
    const int t = blockIdx.x * 256 + threadIdx.x;   // 0..16383
    const int half = t >> 13;                       // 0: W1, 1: W2
    const int u = t & 8191;
    const int lane = u & 31;
    const int p    = (u >> 5) & 1;                  // ntp / ktp
    const int q    = (u >> 6) & 7;                  // kt  / nt
    const int c    = u >> 9;
    const int grp  = lane >> 2;
    const int tig  = lane & 3;

    uint4 hi, lo;
    if (half == 0) {
        // B[k][n] = W1[c][g=n][d=k]; frag words: b0=B[tig][grp], b1=B[tig+4][grp]
        const int kt = q, ntp = p;
        const float* base = W1 + ((size_t)c * Gg) * Dd;
        #pragma unroll
        for (int j = 0; j < 2; j++) {
            const int g = (2 * ntp + j) * 8 + grp;
            float v0 = base[(size_t)g * Dd + kt * 8 + tig];
            float v4 = base[(size_t)g * Dd + kt * 8 + tig + 4];
            uint32_t h0, l0, h4, l4;
            split_tf32(v0, h0, l0);
            split_tf32(v4, h4, l4);
            if (j == 0) { hi.x = h0; hi.y = h4; lo.x = l0; lo.y = l4; }
            else        { hi.z = h0; hi.w = h4; lo.z = l0; lo.w = l4; }
        }
        W1pHi[u] = hi; W1pLo[u] = lo;
    } else {
        // B[k][n] = W2[c][d=n][g=k]
        const int nt = q, ktp = p;
        const float* base = W2 + ((size_t)c * Dd) * Gg;
        const int d = nt * 8 + grp;
        #pragma unroll
        for (int j = 0; j < 2; j++) {
            const int kt = 2 * ktp + j;
            float v0 = base[(size_t)d * Gg + kt * 8 + tig];
            float v4 = base[(size_t)d * Gg + kt * 8 + tig + 4];
            uint32_t h0, l0, h4, l4;
            split_tf32(v0, h0, l0);
            split_tf32(v4, h4, l4);
            if (j == 0) { hi.x = h0; hi.y = h4; lo.x = l0; lo.y = l4; }
            else        { hi.z = h0; hi.w = h4; lo.z = l0; lo.w = l4; }
        }
        W2pHi[u] = hi; W2pLo[u] = lo;
    }
}

extern __shared__ float smem[];

__global__ void __launch_bounds__(NTH, 1)
causal_dag_kernel(const float* __restrict__ x,  const float* __restrict__ A,
                  const float* __restrict__ b1, const float* __restrict__ b2,
                  float* __restrict__ out)
{
    float* m_s = smem;                         // [C][BT][DP] = 34816 floats
    float* A_s = smem + Cc * BT * DP;          // [C][C]

    const int tid = threadIdx.x;
    const int b0  = blockIdx.x * BT;

    if (tid < Cc * Cc) A_s[tid] = A[tid];
    __syncthreads();

    // ---------------- Phase 1: mix (exact fp32, packed FMA) ------------------
    {
        const int bl = tid >> 4;               // 0..31 local batch
        const int dq = tid & 15;               // float4 chunk of D
        const ulonglong2* xb =
            (const ulonglong2*)(x + (size_t)(b0 + bl) * (Cc * Dd)) + dq;

        ull mrx[Cc], mrz[Cc];
        #pragma unroll
        for (int i = 0; i < Cc; i++) { mrx[i] = 0ull; mrz[i] = 0ull; }
        #pragma unroll
        for (int j = 0; j < Cc; j++) {
            ulonglong2 xv = xb[j * 16];
            #pragma unroll
            for (int i = 0; i < Cc; i++) {
                ull a2 = dup2(A_s[j * Cc + i]);
                mrx[i] = fma2(a2, xv.x, mrx[i]);
                mrz[i] = fma2(a2, xv.y, mrz[i]);
            }
        }
        #pragma unroll
        for (int i = 0; i < Cc; i++) {
            ulonglong2 v; v.x = mrx[i]; v.y = mrz[i];
            *(ulonglong2*)&m_s[i * (BT * DP) + bl * DP + dq * 4] = v;
        }
    }
    __syncthreads();

    // ---------------- Phases 2+3: tensor cores, warp = concept ---------------
    const int c    = tid >> 5;                 // warp id == concept (16 warps)
    const int lane = tid & 31;
    const int grp  = lane >> 2;
    const int tig  = lane & 3;
    float* mc = m_s + c * (BT * DP);

    // ---- Phase 2: H[32x32] = ELU(M[32x64] @ W1_c^T + b1) ----
    float acc[2][4][4];
    #pragma unroll
    for (int rt = 0; rt < 2; rt++)
        #pragma unroll
        for (int nt = 0; nt < 4; nt++)
            #pragma unroll
            for (int q = 0; q < 4; q++) acc[rt][nt][q] = 0.0f;

    #pragma unroll
    for (int kt = 0; kt < 8; kt++) {
        const int wi = ((c * 8 + kt) * 2) * 32 + lane;
        const uint4 fh0 = W1pHi[wi];        const uint4 fh1 = W1pHi[wi + 32];
        const uint4 fl0 = W1pLo[wi];        const uint4 fl1 = W1pLo[wi + 32];
        const int colk = kt * 8 + tig;
        #pragma unroll
        for (int rt = 0; rt < 2; rt++) {
            const int r = rt * 16;
            uint32_t ah[4], al[4];
            split_tf32(mc[(r + grp) * DP + colk],          ah[0], al[0]);
            split_tf32(mc[(r + grp + 8) * DP + colk],      ah[1], al[1]);
            split_tf32(mc[(r + grp) * DP + colk + 4],      ah[2], al[2]);
            split_tf32(mc[(r + grp + 8) * DP + colk + 4],  ah[3], al[3]);
            mma3(acc[rt][0], ah, al, fh0.x, fh0.y, fl0.x, fl0.y);
            mma3(acc[rt][1], ah, al, fh0.z, fh0.w, fl0.z, fl0.w);
            mma3(acc[rt][2], ah, al, fh1.x, fh1.y, fl1.x, fl1.y);
            mma3(acc[rt][3], ah, al, fh1.z, fh1.w, fl1.z, fl1.w);
        }
    }

    __syncwarp();                              // m reads done before overwrite
    #pragma unroll
    for (int rt = 0; rt < 2; rt++) {
        const int r = rt * 16;
        #pragma unroll
        for (int nt = 0; nt < 4; nt++) {
            const float2 bias = *(const float2*)&b1[c * Gg + nt * 8 + 2 * tig];
            float h0 = acc[rt][nt][0] + bias.x;
            float h1 = acc[rt][nt][1] + bias.y;
            float h2 = acc[rt][nt][2] + bias.x;
            float h3 = acc[rt][nt][3] + bias.y;
            h0 = h0 > 0.0f ? h0 : expm1f(h0);
            h1 = h1 > 0.0f ? h1 : expm1f(h1);
            h2 = h2 > 0.0f ? h2 : expm1f(h2);
            h3 = h3 > 0.0f ? h3 : expm1f(h3);
            float2 v0; v0.x = h0; v0.y = h1;
            float2 v1; v1.x = h2; v1.y = h3;
            *(float2*)&mc[(r + grp) * HP + nt * 8 + 2 * tig]     = v0;
            *(float2*)&mc[(r + grp + 8) * HP + nt * 8 + 2 * tig] = v1;
        }
    }
    __syncwarp();

    // ---- Phase 3: Out[32x64] = H[32x32] @ W2_c^T + b2 ----
    uint32_t hh[2][4][4], hl[2][4][4];         // hoisted, pre-split H fragments
    #pragma unroll
    for (int rt = 0; rt < 2; rt++) {
        const int r = rt * 16;
        #pragma unroll
        for (int kt = 0; kt < 4; kt++) {
            const int colk = kt * 8 + tig;
            split_tf32(mc[(r + grp) * HP + colk],         hh[rt][kt][0], hl[rt][kt][0]);
            split_tf32(mc[(r + grp + 8) * HP + colk],     hh[rt][kt][1], hl[rt][kt][1]);
            split_tf32(mc[(r + grp) * HP + colk + 4],     hh[rt][kt][2], hl[rt][kt][2]);
            split_tf32(mc[(r + grp + 8) * HP + colk + 4], hh[rt][kt][3], hl[rt][kt][3]);
        }
    }

    #pragma unroll
    for (int nt = 0; nt < 8; nt++) {
        const int wi = ((c * 8 + nt) * 2) * 32 + lane;
        const uint4 gh0 = W2pHi[wi];        const uint4 gh1 = W2pHi[wi + 32];
        const uint4 gl0 = W2pLo[wi];        const uint4 gl1 = W2pLo[wi + 32];
        const float2 bias = *(const float2*)&b2[c * Dd + nt * 8 + 2 * tig];
        #pragma unroll
        for (int rt = 0; rt < 2; rt++) {
            float o[4] = {0.0f, 0.0f, 0.0f, 0.0f};
            mma3(o, hh[rt][0], hl[rt][0], gh0.x, gh0.y, gl0.x, gl0.y);
            mma3(o, hh[rt][1], hl[rt][1], gh0.z, gh0.w, gl0.z, gl0.w);
            mma3(o, hh[rt][2], hl[rt][2], gh1.x, gh1.y, gl1.x, gl1.y);
            mma3(o, hh[rt][3], hl[rt][3], gh1.z, gh1.w, gl1.z, gl1.w);
            const int r = rt * 16;
            float2 v0; v0.x = o[0] + bias.x; v0.y = o[1] + bias.y;
            float2 v1; v1.x = o[2] + bias.x; v1.y = o[3] + bias.y;
            float* op0 = out + ((size_t)(b0 + r + grp) * Cc + c) * Dd + nt * 8 + 2 * tig;
            float* op1 = out + ((size_t)(b0 + r + grp + 8) * Cc + c) * Dd + nt * 8 + 2 * tig;
            *(float2*)op0 = v0;
            *(float2*)op1 = v1;
        }
    }
}

extern "C" void kernel_launch(void* const* d_in, const int* in_sizes, int n_in,
                              void* d_out, int out_size)
{
    const float* x  = (const float*)d_in[0];
    const float* A  = (const float*)d_in[1];
    const float* W1 = (const float*)d_in[2];
    const float* b1 = (const float*)d_in[3];
    const float* W2 = (const float*)d_in[4];
    const float* b2 = (const float*)d_in[5];
    float* out = (float*)d_out;

    const int Btot = in_sizes[0] / (Cc * Dd);                      // 65536
    const int smem_bytes = (Cc * BT * DP + Cc * Cc) * (int)sizeof(float); // 140288

    pack_weights<<<64, 256>>>(W1, W2);

    cudaFuncSetAttribute(causal_dag_kernel,
                         cudaFuncAttributeMaxDynamicSharedMemorySize, smem_bytes);
    causal_dag_kernel<<<Btot / BT, NTH, smem_bytes>>>(x, A, b1, b2, out);
}

// round 8
// speedup vs baseline: 1.6830x; 1.0427x over previous
#include <cuda_runtime.h>
#include <cstdint>

// CausalDAG fused, warp-specialized persistent kernel for GB300 (sm_103a).
//   m[b,i,d]  = sum_j A[j,i] * x[b,j,d]       (producer warps, exact fp32 fma2)
//   h = elu(W1_c @ m + b1); out = W2_c @ h+b2 (consumer warps, TF32 3-mma comp)
//
// One 512-thread CTA per SM (persistent). Warps 0-7 = producers (mix), warps
// 8-15 = consumers (warp owns concepts 2cw, 2cw+1). Ring of two BT=16 m
// buffers + two H regions; named barriers FULL0/1, EMPTY0/1 (count 512).
// Consumers process tile PAIRS so each weight fragment is fetched once per
// two tiles; weights are prepacked as raw fp32 fragments (pack_weights) and
// split to tf32 hi/lo once per pair in registers.

#define Cc 16
#define Dd 64
#define Gg 32
#define DP 68          // m row stride (floats) -> conflict-free fragment LDS
#define HP 36          // h row stride
#define NTH 512

typedef unsigned long long ull;

// Raw fp32 fragment-packed weights: [c][kt|nt (8)][pair (2)][lane (32)]
__device__ uint4 W1p[Cc * 8 * 2 * 32];
__device__ uint4 W2p[Cc * 8 * 2 * 32];

__device__ __forceinline__ ull fma2(ull a, ull b, ull c) {
    ull d;
    asm("fma.rn.f32x2 %0, %1, %2, %3;" : "=l"(d) : "l"(a), "l"(b), "l"(c));
    return d;
}
__device__ __forceinline__ ull dup2(float a) {
    ull d;
    asm("mov.b64 %0, {%1, %1};" : "=l"(d) : "f"(a));
    return d;
}
__device__ __forceinline__ void split_tf32(float v, uint32_t& hi, uint32_t& lo) {
    asm("cvt.rna.tf32.f32 %0, %1;" : "=r"(hi) : "f"(v));
    float r = v - __uint_as_float(hi);
    asm("cvt.rna.tf32.f32 %0, %1;" : "=r"(lo) : "f"(r));
}
__device__ __forceinline__ void mma_tf32(float c[4],
                                         uint32_t a0, uint32_t a1, uint32_t a2, uint32_t a3,
                                         uint32_t b0, uint32_t b1) {
    asm volatile(
        "mma.sync.aligned.m16n8k8.row.col.f32.tf32.tf32.f32 "
        "{%0,%1,%2,%3}, {%4,%5,%6,%7}, {%8,%9}, {%0,%1,%2,%3};"
        : "+f"(c[0]), "+f"(c[1]), "+f"(c[2]), "+f"(c[3])
        : "r"(a0), "r"(a1), "r"(a2), "r"(a3), "r"(b0), "r"(b1));
}
__device__ __forceinline__ void mma3(float c[4],
                                     const uint32_t ah[4], const uint32_t al[4],
                                     uint32_t bh0, uint32_t bh1,
                                     uint32_t bl0, uint32_t bl1) {
    mma_tf32(c, ah[0], ah[1], ah[2], ah[3], bh0, bh1);
    mma_tf32(c, al[0], al[1], al[2], al[3], bh0, bh1);
    mma_tf32(c, ah[0], ah[1], ah[2], ah[3], bl0, bl1);
}
__device__ __forceinline__ float elu1(float v) {
    return v > 0.0f ? v : (__expf(v) - 1.0f);
}

// ---------------- Prep: pack raw fp32 weights into fragment order -----------
__global__ void __launch_bounds__(256)
pack_weights(const float* __restrict__ W1, const float* __restrict__ W2)
{
    const int t = blockIdx.x * 256 + threadIdx.x;   // 0..16383
    const int half = t >> 13;
    const int u = t & 8191;
    const int lane = u & 31;
    const int p    = (u >> 5) & 1;
    const int q    = (u >> 6) & 7;
    const int c    = u >> 9;
    const int grp  = lane >> 2;
    const int tig  = lane & 3;

    uint4 v;
    if (half == 0) {                                // W1: B[k=d][n=g]
        const int kt = q, ntp = p;
        const float* base = W1 + (size_t)c * Gg * Dd;
        const int g0 = (2 * ntp + 0) * 8 + grp;
        const int g1 = (2 * ntp + 1) * 8 + grp;
        v.x = __float_as_uint(base[(size_t)g0 * Dd + kt * 8 + tig]);
        v.y = __float_as_uint(base[(size_t)g0 * Dd + kt * 8 + tig + 4]);
        v.z = __float_as_uint(base[(size_t)g1 * Dd + kt * 8 + tig]);
        v.w = __float_as_uint(base[(size_t)g1 * Dd + kt * 8 + tig + 4]);
        W1p[u] = v;
    } else {                                        // W2: B[k=g][n=d]
        const int nt = q, ktp = p;
        const float* base = W2 + (size_t)c * Dd * Gg;
        const int d = nt * 8 + grp;
        const int k0 = (2 * ktp + 0) * 8;
        const int k1 = (2 * ktp + 1) * 8;
        v.x = __float_as_uint(base[(size_t)d * Gg + k0 + tig]);
        v.y = __float_as_uint(base[(size_t)d * Gg + k0 + tig + 4]);
        v.z = __float_as_uint(base[(size_t)d * Gg + k1 + tig]);
        v.w = __float_as_uint(base[(size_t)d * Gg + k1 + tig + 4]);
        W2p[u] = v;
    }
}

extern __shared__ float smem[];
// layout (floats): mbuf0 [0,17408) mbuf1 [17408,34816)
//                  H0 [34816,44032) H1 [44032,53248)  A [53248,53504)
#define MBUF(t) (smem + (t) * 17408)
#define HBUF(t) (smem + 34816 + (t) * 9216)

__global__ void __launch_bounds__(NTH, 1)
causal_dag_kernel(const float* __restrict__ x,  const float* __restrict__ A,
                  const float* __restrict__ b1, const float* __restrict__ b2,
                  float* __restrict__ out, int nPairs)
{
    const int tid = threadIdx.x;

    if (tid < 256) {
        // ======================= PRODUCER (warps 0-7) ========================
        float* A_s = smem + 53248;
        A_s[tid] = A[tid];
        asm volatile("bar.sync 5, 256;" ::: "memory");

        const int bl = tid >> 4;               // 0..15 local batch row
        const int dq = tid & 15;               // float4 chunk of D=64
        int it = 0;
        for (int p = blockIdx.x; p < nPairs; p += gridDim.x, ++it) {
            #pragma unroll
            for (int sub = 0; sub < 2; sub++) {
                if (it > 0)
                    asm volatile("bar.sync %0, 512;" :: "r"(3 + sub) : "memory");
                const int tile = 2 * p + sub;
                const ulonglong2* xb =
                    (const ulonglong2*)(x + (size_t)(tile * 16 + bl) * (Cc * Dd)) + dq;

                ull mrx[Cc], mrz[Cc];
                #pragma unroll
                for (int i = 0; i < Cc; i++) { mrx[i] = 0ull; mrz[i] = 0ull; }
                #pragma unroll
                for (int j = 0; j < Cc; j++) {
                    ulonglong2 xv = xb[j * 16];
                    #pragma unroll
                    for (int i = 0; i < Cc; i++) {
                        ull a2 = dup2(A_s[j * Cc + i]);
                        mrx[i] = fma2(a2, xv.x, mrx[i]);
                        mrz[i] = fma2(a2, xv.y, mrz[i]);
                    }
                }
                float* buf = MBUF(sub);
                #pragma unroll
                for (int i = 0; i < Cc; i++) {
                    ulonglong2 v; v.x = mrx[i]; v.y = mrz[i];
                    *(ulonglong2*)&buf[i * (16 * DP) + bl * DP + dq * 4] = v;
                }
                asm volatile("bar.arrive %0, 512;" :: "r"(1 + sub) : "memory");
            }
        }
    } else {
        // ======================= CONSUMER (warps 8-15) =======================
        const int cw   = (tid >> 5) - 8;       // 0..7
        const int lane = tid & 31;
        const int grp  = lane >> 2;
        const int tig  = lane & 3;

        for (int p = blockIdx.x; p < nPairs; p += gridDim.x) {
            asm volatile("bar.sync 1, 512;" ::: "memory");
            asm volatile("bar.sync 2, 512;" ::: "memory");

            // ---------- Stage A: phase-2 for both tiles, both concepts -------
            #pragma unroll
            for (int s = 0; s < 2; s++) {
                const int c = 2 * cw + s;
                float acc[2][4][4];
                #pragma unroll
                for (int t = 0; t < 2; t++)
                    #pragma unroll
                    for (int nt = 0; nt < 4; nt++)
                        #pragma unroll
                        for (int q = 0; q < 4; q++) acc[t][nt][q] = 0.0f;

                #pragma unroll
                for (int kt = 0; kt < 8; kt++) {
                    const uint4 f0 = W1p[(c * 8 + kt) * 64 + lane];
                    const uint4 f1 = W1p[(c * 8 + kt) * 64 + 32 + lane];
                    uint32_t bh[8], bl[8];
                    split_tf32(__uint_as_float(f0.x), bh[0], bl[0]);
                    split_tf32(__uint_as_float(f0.y), bh[1], bl[1]);
                    split_tf32(__uint_as_float(f0.z), bh[2], bl[2]);
                    split_tf32(__uint_as_float(f0.w), bh[3], bl[3]);
                    split_tf32(__uint_as_float(f1.x), bh[4], bl[4]);
                    split_tf32(__uint_as_float(f1.y), bh[5], bl[5]);
                    split_tf32(__uint_as_float(f1.z), bh[6], bl[6]);
                    split_tf32(__uint_as_float(f1.w), bh[7], bl[7]);
                    const int colk = kt * 8 + tig;
                    #pragma unroll
                    for (int t = 0; t < 2; t++) {
                        const float* mcp = MBUF(t) + c * (16 * DP);
                        uint32_t ah[4], al[4];
                        split_tf32(mcp[grp * DP + colk],           ah[0], al[0]);
                        split_tf32(mcp[(grp + 8) * DP + colk],     ah[1], al[1]);
                        split_tf32(mcp[grp * DP + colk + 4],       ah[2], al[2]);
                        split_tf32(mcp[(grp + 8) * DP + colk + 4], ah[3], al[3]);
                        mma3(acc[t][0], ah, al, bh[0], bh[1], bl[0], bl[1]);
                        mma3(acc[t][1], ah, al, bh[2], bh[3], bl[2], bl[3]);
                        mma3(acc[t][2], ah, al, bh[4], bh[5], bl[4], bl[5]);
                        mma3(acc[t][3], ah, al, bh[6], bh[7], bl[6], bl[7]);
                    }
                }
                // ELU + bias -> H regions (separate from m buffers)
                #pragma unroll
                for (int t = 0; t < 2; t++) {
                    float* hc = HBUF(t) + c * (16 * HP);
                    #pragma unroll
                    for (int nt = 0; nt < 4; nt++) {
                        const float2 bias = *(const float2*)&b1[c * Gg + nt * 8 + 2 * tig];
                        float2 v0, v1;
                        v0.x = elu1(acc[t][nt][0] + bias.x);
                        v0.y = elu1(acc[t][nt][1] + bias.y);
                        v1.x = elu1(acc[t][nt][2] + bias.x);
                        v1.y = elu1(acc[t][nt][3] + bias.y);
                        *(float2*)&hc[grp * HP + nt * 8 + 2 * tig]       = v0;
                        *(float2*)&hc[(grp + 8) * HP + nt * 8 + 2 * tig] = v1;
                    }
                }
            }
            // m buffers fully consumed -> release to producer
            asm volatile("bar.arrive 3, 512;" ::: "memory");
            asm volatile("bar.arrive 4, 512;" ::: "memory");
            __syncwarp();                      // order H stores vs loads in-warp

            // ---------- Stage B: phase-3 for both tiles, both concepts -------
            #pragma unroll
            for (int s = 0; s < 2; s++) {
                const int c = 2 * cw + s;
                uint32_t hh[2][4][4], hl[2][4][4];
                #pragma unroll
                for (int t = 0; t < 2; t++) {
                    const float* hcp = HBUF(t) + c * (16 * HP);
                    #pragma unroll
                    for (int k2 = 0; k2 < 4; k2++) {
                        const int colk = k2 * 8 + tig;
                        split_tf32(hcp[grp * HP + colk],           hh[t][k2][0], hl[t][k2][0]);
                        split_tf32(hcp[(grp + 8) * HP + colk],     hh[t][k2][1], hl[t][k2][1]);
                        split_tf32(hcp[grp * HP + colk + 4],       hh[t][k2][2], hl[t][k2][2]);
                        split_tf32(hcp[(grp + 8) * HP + colk + 4], hh[t][k2][3], hl[t][k2][3]);
                    }
                }
                #pragma unroll
                for (int nt = 0; nt < 8; nt++) {
                    const uint4 g0 = W2p[(c * 8 + nt) * 64 + lane];
                    const uint4 g1 = W2p[(c * 8 + nt) * 64 + 32 + lane];
                    uint32_t gh[8], gl[8];
                    split_tf32(__uint_as_float(g0.x), gh[0], gl[0]);
                    split_tf32(__uint_as_float(g0.y), gh[1], gl[1]);
                    split_tf32(__uint_as_float(g0.z), gh[2], gl[2]);
                    split_tf32(__uint_as_float(g0.w), gh[3], gl[3]);
                    split_tf32(__uint_as_float(g1.x), gh[4], gl[4]);
                    split_tf32(__uint_as_float(g1.y), gh[5], gl[5]);
                    split_tf32(__uint_as_float(g1.z), gh[6], gl[6]);
                    split_tf32(__uint_as_float(g1.w), gh[7], gl[7]);
                    const float2 bias = *(const float2*)&b2[c * Dd + nt * 8 + 2 * tig];
                    #pragma unroll
                    for (int t = 0; t < 2; t++) {
                        float o[4] = {0.0f, 0.0f, 0.0f, 0.0f};
                        mma3(o, hh[t][0], hl[t][0], gh[0], gh[1], gl[0], gl[1]);
                        mma3(o, hh[t][1], hl[t][1], gh[2], gh[3], gl[2], gl[3]);
                        mma3(o, hh[t][2], hl[t][2], gh[4], gh[5], gl[4], gl[5]);
                        mma3(o, hh[t][3], hl[t][3], gh[6], gh[7], gl[6], gl[7]);
                        const int b0 = (2 * p + t) * 16;
                        float2 v0; v0.x = o[0] + bias.x; v0.y = o[1] + bias.y;
                        float2 v1; v1.x = o[2] + bias.x; v1.y = o[3] + bias.y;
                        *(float2*)(out + ((size_t)(b0 + grp) * Cc + c) * Dd
                                       + nt * 8 + 2 * tig) = v0;
                        *(float2*)(out + ((size_t)(b0 + grp + 8) * Cc + c) * Dd
                                       + nt * 8 + 2 * tig) = v1;
                    }
                }
            }
        }
    }
}

extern "C" void kernel_launch(void* const* d_in, const int* in_sizes, int n_in,
                              void* d_out, int out_size)
{
    const float* x  = (const float*)d_in[0];
    const float* A  = (const float*)d_in[1];
    const float* W1 = (const float*)d_in[2];
    const float* b1 = (const float*)d_in[3];
    const float* W2 = (const float*)d_in[4];
    const float* b2 = (const float*)d_in[5];
    float* out = (float*)d_out;

    const int Btot   = in_sizes[0] / (Cc * Dd);        // 65536
    const int nPairs = Btot / 32;                      // 2048 tile pairs

    int sms = 148;
    cudaDeviceGetAttribute(&sms, cudaDevAttrMultiProcessorCount, 0);

    const int smem_bytes = 53504 * (int)sizeof(float); // 214016 B

    pack_weights<<<64, 256>>>(W1, W2);

    cudaFuncSetAttribute(causal_dag_kernel,
                         cudaFuncAttributeMaxDynamicSharedMemorySize, smem_bytes);
    causal_dag_kernel<<<sms, NTH, smem_bytes>>>(x, A, b1, b2, out, nPairs);
}

// round 9
// speedup vs baseline: 2.3388x; 1.3897x over previous
#include <cuda_runtime.h>
#include <cstdint>

// CausalDAG fused, warp-specialized persistent kernel for GB300 (sm_103a). R8.
//   m = A^T x (producer warps, exact fp32 fma2, emitted as bf16 hi/lo pairs)
//   h = elu(W1_c @ m + b1); out = W2_c @ h + b2   (bf16 m16n8k16, 3-mma comp)
//
// vs R7: bf16 mma halves mma count; producer pre-splits A operand (zero
// consumer cvt); H stays in registers (acc layout == next A-frag layout);
// weights prepacked as bf16 hi/lo fragments; per-tile buffer release.

#define Cc 16
#define Dd 64
#define Gg 32
#define NTH 512
#define ROWU2 36            // uint2 (hi,lo) pairs per row incl. pad -> conflict-free
#define CTU2 (16 * ROWU2)   // uint2 per (concept, tile) block = 576
#define TILEU2 (Cc * CTU2)  // 9216 uint2 = 73728 B per tile buffer

typedef unsigned long long ull;

// Prepacked bf16 hi/lo weight fragments.
// W1pk[((c*4+kt)*4+q)*32+lane], q: 0=hi(nt0,nt1) 1=hi(nt2,nt3) 2=lo(nt0,nt1) 3=lo(nt2,nt3)
// W2pk[((c*8+nt)*2+hl)*32+lane], uint4 = {b0(kt0),b1(kt0),b0(kt1),b1(kt1)}
__device__ uint4 W1pk[Cc * 4 * 4 * 32];
__device__ uint4 W2pk[Cc * 8 * 2 * 32];

__device__ __forceinline__ ull fma2(ull a, ull b, ull c) {
    ull d;
    asm("fma.rn.f32x2 %0, %1, %2, %3;" : "=l"(d) : "l"(a), "l"(b), "l"(c));
    return d;
}
__device__ __forceinline__ ull dup2(float a) {
    ull d;
    asm("mov.b64 %0, {%1, %1};" : "=l"(d) : "f"(a));
    return d;
}
// pack two f32 -> bf16x2, 'lo' lands in lower 16 bits
__device__ __forceinline__ uint32_t pack_bf16_2(float lo, float hi) {
    uint32_t r;
    asm("cvt.rn.bf16x2.f32 %0, %1, %2;" : "=r"(r) : "f"(hi), "f"(lo));
    return r;
}
// fp32 pair -> bf16 hi pair + bf16 lo pair (residual)
__device__ __forceinline__ void split_pair(float f0, float f1,
                                           uint32_t& hi, uint32_t& lo) {
    hi = pack_bf16_2(f0, f1);
    float f0h = __uint_as_float(hi << 16);
    float f1h = __uint_as_float(hi & 0xffff0000u);
    lo = pack_bf16_2(f0 - f0h, f1 - f1h);
}
__device__ __forceinline__ void mma_bf16(float c[4],
                                         uint32_t a0, uint32_t a1, uint32_t a2, uint32_t a3,
                                         uint32_t b0, uint32_t b1) {
    asm volatile(
        "mma.sync.aligned.m16n8k16.row.col.f32.bf16.bf16.f32 "
        "{%0,%1,%2,%3}, {%4,%5,%6,%7}, {%8,%9}, {%0,%1,%2,%3};"
        : "+f"(c[0]), "+f"(c[1]), "+f"(c[2]), "+f"(c[3])
        : "r"(a0), "r"(a1), "r"(a2), "r"(a3), "r"(b0), "r"(b1));
}
__device__ __forceinline__ float elu1(float v) {
    return v > 0.0f ? v : (__expf(v) - 1.0f);
}

// ---------------- Prep: pack weights into bf16 hi/lo fragment order ----------
__global__ void __launch_bounds__(256)
pack_weights(const float* __restrict__ W1, const float* __restrict__ W2)
{
    const int t = blockIdx.x * 256 + threadIdx.x;   // 0..16383
    const int half = t >> 13;
    const int u = t & 8191;
    const int lane = u & 31;
    const int grp  = lane >> 2;
    const int tig  = lane & 3;

    uint4 v;
    if (half == 0) {
        const int q  = (u >> 5) & 3;
        const int kt = (u >> 7) & 3;
        const int c  = u >> 9;
        const bool lo_sel = q >= 2;
        const int ntA = (q & 1) * 2;
        #pragma unroll
        for (int j = 0; j < 2; j++) {
            const int nt = ntA + j;
            const int g  = nt * 8 + grp;
            const float* wr = W1 + ((size_t)c * Gg + g) * Dd + kt * 16 + 2 * tig;
            uint32_t h0, l0, h1, l1;
            split_pair(wr[0], wr[1], h0, l0);       // b0: k = 2tig, 2tig+1
            split_pair(wr[8], wr[9], h1, l1);       // b1: k = 2tig+8, 2tig+9
            if (j == 0) { v.x = lo_sel ? l0 : h0; v.y = lo_sel ? l1 : h1; }
            else        { v.z = lo_sel ? l0 : h0; v.w = lo_sel ? l1 : h1; }
        }
        W1pk[u] = v;
    } else {
        const int hl = (u >> 5) & 1;
        const int nt = (u >> 6) & 7;
        const int c  = u >> 9;
        const int d  = nt * 8 + grp;
        #pragma unroll
        for (int kt = 0; kt < 2; kt++) {
            const float* wr = W2 + ((size_t)c * Dd + d) * Gg + kt * 16 + 2 * tig;
            uint32_t h0, l0, h1, l1;
            split_pair(wr[0], wr[1], h0, l0);
            split_pair(wr[8], wr[9], h1, l1);
            uint32_t e0 = hl ? l0 : h0, e1 = hl ? l1 : h1;
            if (kt == 0) { v.x = e0; v.y = e1; }
            else         { v.z = e0; v.w = e1; }
        }
        W2pk[u] = v;
    }
}

extern __shared__ char smem_raw[];
// [0, 147456): two tile buffers of uint2 (hi,lo) bf16 pairs; [147456,+1K): A_s

__global__ void __launch_bounds__(NTH, 1)
causal_dag_kernel(const float* __restrict__ x,  const float* __restrict__ A,
                  const float* __restrict__ b1, const float* __restrict__ b2,
                  float* __restrict__ out, int nPairs)
{
    uint2* mbuf = (uint2*)smem_raw;
    float* A_s  = (float*)(smem_raw + 2 * TILEU2 * 8);
    const int tid = threadIdx.x;

    if (tid < 256) {
        // ======================= PRODUCER (warps 0-7) ========================
        A_s[tid] = A[tid];
        asm volatile("bar.sync 5, 256;" ::: "memory");

        const int bl = tid >> 4;               // 0..15 local batch row
        const int dq = tid & 15;               // float4 chunk of D=64
        int it = 0;
        for (int p = blockIdx.x; p < nPairs; p += gridDim.x, ++it) {
            #pragma unroll
            for (int sub = 0; sub < 2; sub++) {
                if (it > 0)
                    asm volatile("bar.sync %0, 512;" :: "r"(3 + sub) : "memory");
                const int tile = 2 * p + sub;
                const ulonglong2* xb =
                    (const ulonglong2*)(x + (size_t)(tile * 16 + bl) * (Cc * Dd)) + dq;

                ull mrx[Cc], mrz[Cc];
                #pragma unroll
                for (int i = 0; i < Cc; i++) { mrx[i] = 0ull; mrz[i] = 0ull; }
                #pragma unroll
                for (int j = 0; j < Cc; j++) {
                    ulonglong2 xv = xb[j * 16];
                    #pragma unroll
                    for (int i = 0; i < Cc; i++) {
                        ull a2 = dup2(A_s[j * Cc + i]);
                        mrx[i] = fma2(a2, xv.x, mrx[i]);
                        mrz[i] = fma2(a2, xv.y, mrz[i]);
                    }
                }
                uint2* buf = mbuf + sub * TILEU2;
                #pragma unroll
                for (int i = 0; i < Cc; i++) {
                    float f0, f1, g0, g1;
                    asm("mov.b64 {%0, %1}, %2;" : "=f"(f0), "=f"(f1) : "l"(mrx[i]));
                    asm("mov.b64 {%0, %1}, %2;" : "=f"(g0), "=f"(g1) : "l"(mrz[i]));
                    uint4 v;
                    split_pair(f0, f1, v.x, v.y);   // pair 2dq   : {hi, lo}
                    split_pair(g0, g1, v.z, v.w);   // pair 2dq+1 : {hi, lo}
                    *(uint4*)&buf[(i * 16 + bl) * ROWU2 + 2 * dq] = v;
                }
                asm volatile("bar.arrive %0, 512;" :: "r"(1 + sub) : "memory");
            }
        }
    } else {
        // ======================= CONSUMER (warps 8-15) =======================
        const int cw   = (tid >> 5) - 8;       // 0..7, owns concepts 2cw,2cw+1
        const int lane = tid & 31;
        const int grp  = lane >> 2;
        const int tig  = lane & 3;

        for (int p = blockIdx.x; p < nPairs; p += gridDim.x) {
            uint32_t hfh[2][2][8], hfl[2][2][8];   // [s][t][kt'*4+r] bf16 pairs

            #pragma unroll
            for (int t = 0; t < 2; t++) {
                asm volatile("bar.sync %0, 512;" :: "r"(1 + t) : "memory");
                #pragma unroll
                for (int s = 0; s < 2; s++) {
                    const int c = 2 * cw + s;
                    const uint2* mc = mbuf + t * TILEU2 + c * CTU2;

                    float acc[4][4];
                    #pragma unroll
                    for (int nt = 0; nt < 4; nt++)
                        #pragma unroll
                        for (int q = 0; q < 4; q++) acc[nt][q] = 0.0f;

                    #pragma unroll
                    for (int kt = 0; kt < 4; kt++) {
                        const int pi = kt * 8 + tig;
                        const uint2 a0 = mc[grp * ROWU2 + pi];
                        const uint2 a1 = mc[(grp + 8) * ROWU2 + pi];
                        const uint2 a2 = mc[grp * ROWU2 + pi + 4];
                        const uint2 a3 = mc[(grp + 8) * ROWU2 + pi + 4];
                        const int wb = ((c * 4 + kt) * 4) * 32 + lane;
                        const uint4 q0 = W1pk[wb];
                        const uint4 q1 = W1pk[wb + 32];
                        const uint4 q2 = W1pk[wb + 64];
                        const uint4 q3 = W1pk[wb + 96];
                        // nt0
                        mma_bf16(acc[0], a0.x, a1.x, a2.x, a3.x, q0.x, q0.y);
                        mma_bf16(acc[0], a0.y, a1.y, a2.y, a3.y, q0.x, q0.y);
                        mma_bf16(acc[0], a0.x, a1.x, a2.x, a3.x, q2.x, q2.y);
                        // nt1
                        mma_bf16(acc[1], a0.x, a1.x, a2.x, a3.x, q0.z, q0.w);
                        mma_bf16(acc[1], a0.y, a1.y, a2.y, a3.y, q0.z, q0.w);
                        mma_bf16(acc[1], a0.x, a1.x, a2.x, a3.x, q2.z, q2.w);
                        // nt2
                        mma_bf16(acc[2], a0.x, a1.x, a2.x, a3.x, q1.x, q1.y);
                        mma_bf16(acc[2], a0.y, a1.y, a2.y, a3.y, q1.x, q1.y);
                        mma_bf16(acc[2], a0.x, a1.x, a2.x, a3.x, q3.x, q3.y);
                        // nt3
                        mma_bf16(acc[3], a0.x, a1.x, a2.x, a3.x, q1.z, q1.w);
                        mma_bf16(acc[3], a0.y, a1.y, a2.y, a3.y, q1.z, q1.w);
                        mma_bf16(acc[3], a0.x, a1.x, a2.x, a3.x, q3.z, q3.w);
                    }
                    // bias + ELU + split to bf16 hi/lo (phase-3 A fragments)
                    #pragma unroll
                    for (int nt = 0; nt < 4; nt++) {
                        const float2 bias = *(const float2*)&b1[c * Gg + nt * 8 + 2 * tig];
                        float v0 = elu1(acc[nt][0] + bias.x);
                        float v1 = elu1(acc[nt][1] + bias.y);
                        float v2 = elu1(acc[nt][2] + bias.x);
                        float v3 = elu1(acc[nt][3] + bias.y);
                        split_pair(v0, v1, hfh[s][t][2 * nt],     hfl[s][t][2 * nt]);
                        split_pair(v2, v3, hfh[s][t][2 * nt + 1], hfl[s][t][2 * nt + 1]);
                    }
                }
                asm volatile("bar.arrive %0, 512;" :: "r"(3 + t) : "memory");
            }

            // ---------- Phase 3: Out = H @ W2^T + b2 (registers only) --------
            #pragma unroll
            for (int s = 0; s < 2; s++) {
                const int c = 2 * cw + s;
                #pragma unroll
                for (int nt = 0; nt < 8; nt++) {
                    const int wb = ((c * 8 + nt) * 2) * 32 + lane;
                    const uint4 gh = W2pk[wb];
                    const uint4 gl = W2pk[wb + 32];
                    const float2 bias = *(const float2*)&b2[c * Dd + nt * 8 + 2 * tig];
                    #pragma unroll
                    for (int t = 0; t < 2; t++) {
                        const uint32_t* hh = hfh[s][t];
                        const uint32_t* hl = hfl[s][t];
                        float o[4] = {0.0f, 0.0f, 0.0f, 0.0f};
                        // kt'=0
                        mma_bf16(o, hh[0], hh[1], hh[2], hh[3], gh.x, gh.y);
                        mma_bf16(o, hl[0], hl[1], hl[2], hl[3], gh.x, gh.y);
                        mma_bf16(o, hh[0], hh[1], hh[2], hh[3], gl.x, gl.y);
                        // kt'=1
                        mma_bf16(o, hh[4], hh[5], hh[6], hh[7], gh.z, gh.w);
                        mma_bf16(o, hl[4], hl[5], hl[6], hl[7], gh.z, gh.w);
                        mma_bf16(o, hh[4], hh[5], hh[6], hh[7], gl.z, gl.w);

                        const int b0 = (2 * p + t) * 16;
                        float2 v0; v0.x = o[0] + bias.x; v0.y = o[1] + bias.y;
                        float2 v1; v1.x = o[2] + bias.x; v1.y = o[3] + bias.y;
                        *(float2*)(out + ((size_t)(b0 + grp) * Cc + c) * Dd
                                       + nt * 8 + 2 * tig) = v0;
                        *(float2*)(out + ((size_t)(b0 + grp + 8) * Cc + c) * Dd
                                       + nt * 8 + 2 * tig) = v1;
                    }
                }
            }
        }
    }
}

extern "C" void kernel_launch(void* const* d_in, const int* in_sizes, int n_in,
                              void* d_out, int out_size)
{
    const float* x  = (const float*)d_in[0];
    const float* A  = (const float*)d_in[1];
    const float* W1 = (const float*)d_in[2];
    const float* b1 = (const float*)d_in[3];
    const float* W2 = (const float*)d_in[4];
    const float* b2 = (const float*)d_in[5];
    float* out = (float*)d_out;

    const int Btot   = in_sizes[0] / (Cc * Dd);        // 65536
    const int nPairs = Btot / 32;                      // 2048

    int sms = 148;
    cudaDeviceGetAttribute(&sms, cudaDevAttrMultiProcessorCount, 0);

    const int smem_bytes = 2 * TILEU2 * 8 + 1024;      // 148480 B

    pack_weights<<<64, 256>>>(W1, W2);

    cudaFuncSetAttribute(causal_dag_kernel,
                         cudaFuncAttributeMaxDynamicSharedMemorySize, smem_bytes);
    causal_dag_kernel<<<sms, NTH, smem_bytes>>>(x, A, b1, b2, out, nPairs);
}